// round 16
// baseline (speedup 1.0000x reference)
#include <cuda_runtime.h>
#include <math.h>

// GAT layer, fully collapsed, ONE persistent kernel, attention phase spread
// across all 64 blocks (8 per batch) with the bucket structure in L2:
//   A: scores s1,s2 + per-block min/max partials (64 blk)
//   B: histogram + exp payload bin-sums via L2 atomics (64 blk, 256 elem each)
//   C: quad scan (cnt2,cnt1,rawA2,rawB2) -> off2,off1,binA2,binB2 (8 blk)
//   D: scatter keys+payloads into bin order (64 blk)
//   F: pass-1 queries -> g1,g2 (64 blk; exps spread across SMs)
//   G: dual scan raw1 -> binA1,binB1 (8 blk)
//   H: pass-2 queries -> c_j (64 blk, c staged in smem)
//   wsum: v = c^T h (64 blk)   out: (v@W)/N (8 blk)
// Max-shift dropped: g1 = e^{s1}/(e^{s1}Apos + e^{.2 s1}SB) — the e^{-m}
// factor cancels exactly; values are O(e^{±2}), no overflow. Branch
// selection (v <= -s) stays an exact fp compare.

#define B 8
#define N 2048
#define FIN 128
#define FOUT 64
#define ALPHA 0.2f
#define NB 1024
#define NB1 (NB + 1)
#define NBLK 64
#define NT 1024

__device__ float d_s1[B * N], d_s2[B * N], d_v[B * FIN];
__device__ float d_pmm[NBLK * 4];
__device__ int   g_cnt2[B * NB], g_cnt1[B * NB];
__device__ float g_rawA2[B * NB], g_rawB2[B * NB], g_rawA1[B * NB], g_rawB1[B * NB];
__device__ int   g_off2[B * NB1], g_off1[B * NB1];
__device__ float g_binA2[B * NB], g_binB2[B * NB], g_binA1[B * NB], g_binB1[B * NB];
__device__ float g_val2[B * N], g_pA2[B * N], g_pB2[B * N];
__device__ float g_val1[B * N], g_pA1[B * N], g_pB1[B * N];
__device__ float g_tot[B * 4];
__device__ unsigned int d_bar[8];   // monotonic ticket counters (never reset)

__device__ __forceinline__ int binOf(float x, float lo, float scale) {
    float f = (x - lo) * scale;
    f = fminf(fmaxf(f, 0.f), (float)(NB - 1));
    return (int)f;
}

// grid-wide barrier, replay-safe: counters only increase; each use adds NBLK.
__device__ __forceinline__ void gsync(int i) {
    __threadfence();
    __syncthreads();
    if (threadIdx.x == 0) {
        unsigned int old = atomicAdd(&d_bar[i], 1u);
        unsigned int target = (old / NBLK + 1u) * NBLK;
        volatile unsigned int* vc = (volatile unsigned int*)&d_bar[i];
        while (*vc < target) { }
    }
    __syncthreads();
}

__global__ void __launch_bounds__(NT, 1) k_fused(
    const float* __restrict__ h, const float* __restrict__ W,
    const float* __restrict__ a, float* __restrict__ out)
{
    int tid = threadIdx.x;
    int lane = tid & 31, wid = tid >> 5;
    int blk = blockIdx.x;
    int b = blk >> 3;           // batch of this block (phases B,D,F,H,wsum)
    int sub = blk & 7;          // sub-block within batch

    __shared__ float sm[5120];                       // 20KB multi-purpose
    __shared__ float wsA[32], wsB[32];
    __shared__ int   wsI[32], wsJ[32];

    // ================= A: zero scratch, scores, min/max partials ==========
    {
        if (tid < 128) {
            g_cnt2[blk * 128 + tid] = 0;  g_cnt1[blk * 128 + tid] = 0;
            g_rawA2[blk * 128 + tid] = 0.f; g_rawB2[blk * 128 + tid] = 0.f;
            g_rawA1[blk * 128 + tid] = 0.f; g_rawB1[blk * 128 + tid] = 0.f;
        }
        if (blk == 0) d_v[tid] = 0.f;

        float* su1 = sm; float* su2 = sm + FIN;
        if (tid < 256) {
            int t = tid & 127;
            const float4* W4 = (const float4*)W;
            const float* av = a + ((tid < 128) ? 0 : FOUT);
            float acc = 0.f;
#pragma unroll
            for (int q = 0; q < 16; q++) {
                float4 w = W4[t * 16 + q];
                acc += w.x * av[q * 4] + w.y * av[q * 4 + 1] +
                       w.z * av[q * 4 + 2] + w.w * av[q * 4 + 3];
            }
            if (tid < 128) su1[t] = acc; else su2[t] = acc;
        }
        __syncthreads();

        int c = lane * 4;
        float u1a = su1[c], u1b = su1[c + 1], u1c = su1[c + 2], u1d = su1[c + 3];
        float u2a = su2[c], u2b = su2[c + 1], u2c = su2[c + 2], u2d = su2[c + 3];
        const float4* h4 = (const float4*)h;
        int row0 = blk * 256 + wid * 8;              // 8 rows per warp
        float mn1 = 1e30f, mx1 = -1e30f, mn2 = 1e30f, mx2 = -1e30f;
#pragma unroll
        for (int g = 0; g < 2; g++) {
            float4 hv[4];
#pragma unroll
            for (int r = 0; r < 4; r++)
                hv[r] = h4[(size_t)(row0 + g * 4 + r) * (FIN / 4) + lane];
#pragma unroll
            for (int r = 0; r < 4; r++) {
                float a1 = hv[r].x * u1a + hv[r].y * u1b + hv[r].z * u1c + hv[r].w * u1d;
                float a2 = hv[r].x * u2a + hv[r].y * u2b + hv[r].z * u2c + hv[r].w * u2d;
#pragma unroll
                for (int o = 16; o; o >>= 1) {
                    a1 += __shfl_xor_sync(0xffffffffu, a1, o);
                    a2 += __shfl_xor_sync(0xffffffffu, a2, o);
                }
                mn1 = fminf(mn1, a1); mx1 = fmaxf(mx1, a1);
                mn2 = fminf(mn2, a2); mx2 = fmaxf(mx2, a2);
                if (lane == 0) {
                    d_s1[row0 + g * 4 + r] = a1;
                    d_s2[row0 + g * 4 + r] = a2;
                }
            }
        }
        if (lane == 0) {
            sm[512 + wid] = mn1; sm[544 + wid] = mx1;
            sm[576 + wid] = mn2; sm[608 + wid] = mx2;
        }
        __syncthreads();
        if (wid == 0) {
            float v0 = sm[512 + lane], v1 = sm[544 + lane];
            float v2 = sm[576 + lane], v3 = sm[608 + lane];
#pragma unroll
            for (int o = 16; o; o >>= 1) {
                v0 = fminf(v0, __shfl_xor_sync(0xffffffffu, v0, o));
                v1 = fmaxf(v1, __shfl_xor_sync(0xffffffffu, v1, o));
                v2 = fminf(v2, __shfl_xor_sync(0xffffffffu, v2, o));
                v3 = fmaxf(v3, __shfl_xor_sync(0xffffffffu, v3, o));
            }
            if (lane == 0) {
                d_pmm[blk * 4 + 0] = v0; d_pmm[blk * 4 + 1] = v1;
                d_pmm[blk * 4 + 2] = v2; d_pmm[blk * 4 + 3] = v3;
            }
        }
    }
    gsync(0);

    // ================= B: histogram + exp payload atomics (tid<256) =======
    float s1 = 0.f, s2 = 0.f, eA = 0.f, eB = 0.f;
    float lo1 = 0.f, lo2 = 0.f, sc1 = 0.f, sc2 = 0.f;
    int bn1 = 0, bn2 = 0, rk1 = 0, rk2 = 0, j = 0, q = 0;
    if (tid < 256) {
        lo1 = 1e30f; lo2 = 1e30f;
        float hi1 = -1e30f, hi2 = -1e30f;
#pragma unroll
        for (int g = 0; g < 8; g++) {
            lo1 = fminf(lo1, __ldcg(&d_pmm[(b * 8 + g) * 4 + 0]));
            hi1 = fmaxf(hi1, __ldcg(&d_pmm[(b * 8 + g) * 4 + 1]));
            lo2 = fminf(lo2, __ldcg(&d_pmm[(b * 8 + g) * 4 + 2]));
            hi2 = fmaxf(hi2, __ldcg(&d_pmm[(b * 8 + g) * 4 + 3]));
        }
        sc1 = (hi1 > lo1) ? ((float)NB / (hi1 - lo1)) : 0.f;
        sc2 = (hi2 > lo2) ? ((float)NB / (hi2 - lo2)) : 0.f;
        j = sub * 256 + tid;
        s1 = __ldcg(&d_s1[b * N + j]);
        s2 = __ldcg(&d_s2[b * N + j]);
        eA = __expf(s2);
        eB = __expf(ALPHA * s2);
        bn2 = binOf(s2, lo2, sc2);
        bn1 = binOf(s1, lo1, sc1);
        rk2 = atomicAdd(&g_cnt2[b * NB + bn2], 1);
        rk1 = atomicAdd(&g_cnt1[b * NB + bn1], 1);
        atomicAdd(&g_rawA2[b * NB + bn2], eA);
        atomicAdd(&g_rawB2[b * NB + bn2], eB);
    }
    gsync(1);

    // ================= C: quad scan -> off2, off1, binA2, binB2 (8 blk) ===
    if (blk < B) {
        int bb = blk;
        int c2 = __ldcg(&g_cnt2[bb * NB + tid]);
        int c1 = __ldcg(&g_cnt1[bb * NB + tid]);
        float f2 = __ldcg(&g_rawA2[bb * NB + tid]);
        float f3 = __ldcg(&g_rawB2[bb * NB + tid]);
        int i2 = c2, i1 = c1; float ia = f2, ib = f3;
#pragma unroll
        for (int o = 1; o < 32; o <<= 1) {
            int y2 = __shfl_up_sync(0xffffffffu, i2, o);
            int y1 = __shfl_up_sync(0xffffffffu, i1, o);
            float ya = __shfl_up_sync(0xffffffffu, ia, o);
            float yb = __shfl_up_sync(0xffffffffu, ib, o);
            if (lane >= o) { i2 += y2; i1 += y1; ia += ya; ib += yb; }
        }
        if (lane == 31) { wsI[wid] = i2; wsJ[wid] = i1; wsA[wid] = ia; wsB[wid] = ib; }
        __syncthreads();
        if (wid == 0) {
            int w2 = wsI[lane], w1 = wsJ[lane];
            float wa = wsA[lane], wb = wsB[lane];
            int j2 = w2, j1 = w1; float ja = wa, jb = wb;
#pragma unroll
            for (int o = 1; o < 32; o <<= 1) {
                int y2 = __shfl_up_sync(0xffffffffu, j2, o);
                int y1 = __shfl_up_sync(0xffffffffu, j1, o);
                float ya = __shfl_up_sync(0xffffffffu, ja, o);
                float yb = __shfl_up_sync(0xffffffffu, jb, o);
                if (lane >= o) { j2 += y2; j1 += y1; ja += ya; jb += yb; }
            }
            wsI[lane] = j2 - w2; wsJ[lane] = j1 - w1;
            wsA[lane] = ja - wa; wsB[lane] = jb - wb;
            if (lane == 31) { g_tot[bb * 4 + 0] = ja; g_tot[bb * 4 + 1] = jb; }
        }
        __syncthreads();
        g_off2[bb * NB1 + tid] = i2 - c2 + wsI[wid];
        g_off1[bb * NB1 + tid] = i1 - c1 + wsJ[wid];
        g_binA2[bb * NB + tid] = ia - f2 + wsA[wid];
        g_binB2[bb * NB + tid] = ib - f3 + wsB[wid];
        if (tid == 0) { g_off2[bb * NB1 + NB] = N; g_off1[bb * NB1 + NB] = N; }
    }
    gsync(2);

    // ================= D: scatter (tid<256) =================
    if (tid < 256) {
        int p = __ldcg(&g_off2[b * NB1 + bn2]) + rk2;
        g_val2[b * N + p] = s2; g_pA2[b * N + p] = eA; g_pB2[b * N + p] = eB;
        q = __ldcg(&g_off1[b * NB1 + bn1]) + rk1;
        g_val1[b * N + q] = s1;
    }
    gsync(3);

    // ================= F: pass-1 queries -> g (tid<256) =================
    if (tid < 256) {
        float tA = __ldcg(&g_tot[b * 4 + 0]);
        float tB = __ldcg(&g_tot[b * 4 + 1]);
        float t = -s1;
        int qb = binOf(t, lo2, sc2);
        float SA = __ldcg(&g_binA2[b * NB + qb]);
        float SB = __ldcg(&g_binB2[b * NB + qb]);
        int ps = __ldcg(&g_off2[b * NB1 + qb]);
        int pe = __ldcg(&g_off2[b * NB1 + qb + 1]);
        for (int p = ps; p < pe; p++) {
            float v = __ldcg(&g_val2[b * N + p]);
            if (v <= t) { SA += __ldcg(&g_pA2[b * N + p]); SB += __ldcg(&g_pB2[b * N + p]); }
        }
        float Apos = tA - SA;               // sum e^{s2} over s2 > -s1
        float eS1 = __expf(s1), eSa = __expf(ALPHA * s1);
        float inv = 1.0f / (eS1 * Apos + eSa * SB);
        float gg1 = eS1 * inv, gg2 = eSa * inv;
        g_pA1[b * N + q] = gg1;
        g_pB1[b * N + q] = gg2;
        atomicAdd(&g_rawA1[b * NB + bn1], gg1);
        atomicAdd(&g_rawB1[b * NB + bn1], gg2);
    }
    gsync(4);

    // ================= G: dual scan raw1 -> binA1, binB1 (8 blk) ==========
    if (blk < B) {
        int bb = blk;
        float f0 = __ldcg(&g_rawA1[bb * NB + tid]);
        float f1 = __ldcg(&g_rawB1[bb * NB + tid]);
        float ia = f0, ib = f1;
#pragma unroll
        for (int o = 1; o < 32; o <<= 1) {
            float ya = __shfl_up_sync(0xffffffffu, ia, o);
            float yb = __shfl_up_sync(0xffffffffu, ib, o);
            if (lane >= o) { ia += ya; ib += yb; }
        }
        if (lane == 31) { wsA[wid] = ia; wsB[wid] = ib; }
        __syncthreads();
        if (wid == 0) {
            float wa = wsA[lane], wb = wsB[lane];
            float ja = wa, jb = wb;
#pragma unroll
            for (int o = 1; o < 32; o <<= 1) {
                float ya = __shfl_up_sync(0xffffffffu, ja, o);
                float yb = __shfl_up_sync(0xffffffffu, jb, o);
                if (lane >= o) { ja += ya; jb += yb; }
            }
            wsA[lane] = ja - wa; wsB[lane] = jb - wb;
            if (lane == 31) { g_tot[bb * 4 + 2] = ja; g_tot[bb * 4 + 3] = jb; }
        }
        __syncthreads();
        g_binA1[bb * NB + tid] = ia - f0 + wsA[wid];
        g_binB1[bb * NB + tid] = ib - f1 + wsB[wid];
    }
    gsync(5);

    // ================= H: pass-2 queries -> c (smem staged, tid<256) ======
    if (tid < 256) {
        float tG1 = __ldcg(&g_tot[b * 4 + 2]);
        float tG2 = __ldcg(&g_tot[b * 4 + 3]);
        float t = -s2;
        int qb = binOf(t, lo1, sc1);
        float SG1 = __ldcg(&g_binA1[b * NB + qb]);
        float SG2 = __ldcg(&g_binB1[b * NB + qb]);
        int ps = __ldcg(&g_off1[b * NB1 + qb]);
        int pe = __ldcg(&g_off1[b * NB1 + qb + 1]);
        for (int p = ps; p < pe; p++) {
            float v = __ldcg(&g_val1[b * N + p]);
            if (v <= t) { SG1 += __ldcg(&g_pA1[b * N + p]); SG2 += __ldcg(&g_pB1[b * N + p]); }
        }
        float P = tG1 - SG1;                // sum g1 over s1 > -s2
        sm[4096 + tid] = eA * P + eB * SG2; // c_j staged in smem (block-local)
    }
    __syncthreads();                        // block-local: wsum uses own c's

    // ================= wsum: v = c^T h (all 64 blocks) =================
    {
        float* red = sm;                    // 32 warps x 128 = 16KB
        const float4* h4 = (const float4*)h;
        size_t base = (size_t)b * N * (FIN / 4);
        int j0 = sub * 256 + wid * 8;
        float4 acc = make_float4(0.f, 0.f, 0.f, 0.f);
#pragma unroll
        for (int r = 0; r < 8; r++) {
            int jj = j0 + r;
            float cj = sm[4096 + wid * 8 + r];
            float4 hv = h4[base + (size_t)jj * (FIN / 4) + lane];
            acc.x = fmaf(cj, hv.x, acc.x);
            acc.y = fmaf(cj, hv.y, acc.y);
            acc.z = fmaf(cj, hv.z, acc.z);
            acc.w = fmaf(cj, hv.w, acc.w);
        }
        ((float4*)red)[wid * 32 + lane] = acc;
        __syncthreads();
        if (tid < FIN) {
            float s = 0.f;
#pragma unroll
            for (int w = 0; w < 32; w++) s += red[w * FIN + tid];
            atomicAdd(&d_v[b * FIN + tid], s);
        }
    }
    gsync(6);

    // ================= out: (v @ W)/N (blocks 0..7) =================
    if (blk < B) {
        int bb = blk;
        float* sv = sm; float* part = sm + FIN;
        if (tid < FIN) sv[tid] = __ldcg(&d_v[bb * FIN + tid]);
        __syncthreads();
        int f = tid & 63, kg = tid >> 6;     // 16 k-groups of 8
        float acc = 0.f;
#pragma unroll
        for (int qq = 0; qq < 8; qq++) {
            int k = kg * 8 + qq;
            acc = fmaf(sv[k], W[k * FOUT + f], acc);
        }
        part[kg * FOUT + f] = acc;
        __syncthreads();
        if (tid < FOUT) {
            float s = 0.f;
#pragma unroll
            for (int g = 0; g < 16; g++) s += part[g * FOUT + tid];
            out[bb * FOUT + tid] = s * (1.0f / (float)N);
        }
    }
}

extern "C" void kernel_launch(void* const* d_in, const int* in_sizes, int n_in,
                              void* d_out, int out_size) {
    (void)in_sizes; (void)n_in; (void)out_size;
    const float* h = (const float*)d_in[0];
    const float* W = (const float*)d_in[1];
    const float* a = (const float*)d_in[2];
    float* out = (float*)d_out;

    k_fused<<<NBLK, NT>>>(h, W, a, out);
}

// round 17
// speedup vs baseline: 1.3384x; 1.3384x over previous
#include <cuda_runtime.h>
#include <cuda_bf16.h>
#include <math.h>

// GAT layer, fully collapsed:
//   s1 = h @ (W a1), s2 = h @ (W a2)
//   Z_i = e^{s1_i} * SUM_{s2_j > -s1_i} e^{s2_j} + e^{.2 s1_i} * SUM_{s2_j <= -s1_i} e^{.2 s2_j}
//   (max-shift cancels exactly in g = e/Z; s-values are O(+-1))
//   c_j = e^{s2_j} * SUM_{s1_i > -s2_j} g1_i + e^{.2 s2_j} * SUM_{s1_i <= -s2_j} g2_i
//   out[b] = (1/N) * (c^T h) @ W
// R17: all exps PRECOMPUTED in k_scores (128 blocks, MUFU-free) and loaded by
// k_attn, whose MUFU budget drops to 1 RCP/element. Bucket structure (R14
// dual-skeleton, scalar arrays) unchanged. Branch selection exact fp compare.

#define B 8
#define N 2048
#define FIN 128
#define FOUT 64
#define ALPHA 0.2f
#define NB 1024

// dynamic smem: val2,pA2,pB2,val1,pA1,pB1 [N]; binA,binB [NB];
//               cnt2,cnt1 [NB] int; off2,off1 [NB+1] int
#define SMEM_ATTN (6 * N * 4 + 2 * NB * 4 + 2 * NB * 4 + 2 * (NB + 1) * 4)

__device__ float d_s1[B * N], d_s2[B * N];
__device__ float d_eA1[B * N], d_eB1[B * N];   // e^{s1}, e^{0.2 s1}
__device__ float d_eA2[B * N], d_eB2[B * N];   // e^{s2}, e^{0.2 s2}
__device__ float d_c[B * N];
__device__ float d_v[B * FIN];

__device__ __forceinline__ int binOf(float x, float lo, float scale) {
    float f = (x - lo) * scale;
    f = fminf(fmaxf(f, 0.f), (float)(NB - 1));
    return (int)f;
}

// ---------------- K1: scores + ALL exps; u = W·a computed per block ----------
// grid = 128 blocks x 256 threads
__global__ void k_scores(const float* __restrict__ h, const float* __restrict__ W,
                         const float* __restrict__ a) {
    __shared__ float su1[FIN], su2[FIN];
    int tid = threadIdx.x;          // 256 threads = 8 warps
    {
        int t = tid & 127;
        const float4* W4 = (const float4*)W;
        const float* av = a + ((tid < 128) ? 0 : FOUT);
        float acc = 0.f;
#pragma unroll
        for (int q = 0; q < 16; q++) {
            float4 w = W4[t * 16 + q];
            acc += w.x * av[q * 4] + w.y * av[q * 4 + 1] +
                   w.z * av[q * 4 + 2] + w.w * av[q * 4 + 3];
        }
        if (tid < 128) su1[t] = acc; else su2[t] = acc;
    }
    __syncthreads();

    int warp = tid >> 5, lane = tid & 31;
    int c = lane * 4;
    float u1a = su1[c], u1b = su1[c + 1], u1c = su1[c + 2], u1d = su1[c + 3];
    float u2a = su2[c], u2b = su2[c + 1], u2c = su2[c + 2], u2d = su2[c + 3];

    const float4* h4 = (const float4*)h;
    int row0 = blockIdx.x * 128 + warp * 16;       // 16 rows per warp
#pragma unroll
    for (int g = 0; g < 4; g++) {
        float4 hv[4];
#pragma unroll
        for (int r = 0; r < 4; r++)
            hv[r] = h4[(size_t)(row0 + g * 4 + r) * (FIN / 4) + lane];
#pragma unroll
        for (int r = 0; r < 4; r++) {
            float a1 = hv[r].x * u1a + hv[r].y * u1b + hv[r].z * u1c + hv[r].w * u1d;
            float a2 = hv[r].x * u2a + hv[r].y * u2b + hv[r].z * u2c + hv[r].w * u2d;
#pragma unroll
            for (int o = 16; o; o >>= 1) {
                a1 += __shfl_xor_sync(0xffffffffu, a1, o);
                a2 += __shfl_xor_sync(0xffffffffu, a2, o);
            }
            if (lane == 0) {
                int row = row0 + g * 4 + r;
                d_s1[row] = a1;
                d_s2[row] = a2;
                d_eA1[row] = __expf(a1);
                d_eB1[row] = __expf(ALPHA * a1);
                d_eA2[row] = __expf(a2);
                d_eB2[row] = __expf(ALPHA * a2);
            }
        }
    }
}

// gather per-bin payload sums, exclusive-scan 1024 bins. totals -> bc[4],bc[5].
__device__ __forceinline__ void binscan(
    const float* pA, const float* pB, const int* off,
    float* binA, float* binB, float* wsA, float* wsB, volatile float* bc,
    int tid, int lane, int wid)
{
    int s = off[tid], e = off[tid + 1];
    float sa = 0.f, sb = 0.f;
    for (int p = s; p < e; p++) { sa += pA[p]; sb += pB[p]; }
    float ia = sa, ib = sb;
#pragma unroll
    for (int o = 1; o < 32; o <<= 1) {
        float ay = __shfl_up_sync(0xffffffffu, ia, o);
        float by = __shfl_up_sync(0xffffffffu, ib, o);
        if (lane >= o) { ia += ay; ib += by; }
    }
    if (lane == 31) { wsA[wid] = ia; wsB[wid] = ib; }
    __syncthreads();
    if (wid == 0) {
        float aw = wsA[lane], bw = wsB[lane];
        float awi = aw, bwi = bw;
#pragma unroll
        for (int o = 1; o < 32; o <<= 1) {
            float ay = __shfl_up_sync(0xffffffffu, awi, o);
            float by = __shfl_up_sync(0xffffffffu, bwi, o);
            if (lane >= o) { awi += ay; bwi += by; }
        }
        wsA[lane] = awi - aw; wsB[lane] = bwi - bw;
        if (lane == 31) { bc[4] = awi; bc[5] = bwi; }
    }
    __syncthreads();
    binA[tid] = ia - sa + wsA[wid];
    binB[tid] = ib - sb + wsB[wid];
}

// ---------------- K2: per-batch softmax column mass c[j] ----------------
__global__ void __launch_bounds__(1024, 1) k_attn() {
    int b = blockIdx.x;
    int tid = threadIdx.x;          // 1024
    int lane = tid & 31, wid = tid >> 5;

    extern __shared__ __align__(16) char dyn[];
    float* val2 = (float*)dyn;
    float* pA2  = val2 + N;
    float* pB2  = pA2 + N;
    float* val1 = pB2 + N;
    float* pA1  = val1 + N;
    float* pB1  = pA1 + N;
    float* binA = pB1 + N;
    float* binB = binA + NB;
    int*   cnt2 = (int*)(binB + NB);
    int*   cnt1 = cnt2 + NB;
    int*   off2 = cnt1 + NB;
    int*   off1 = off2 + (NB + 1);

    __shared__ float wsA[32], wsB[32];
    __shared__ int   wsI[32], wsJ[32];
    __shared__ float bc[8];   // lo2,hi2,lo1,hi1,totA,totB

    float rs1[2], rs2[2], reA1[2], reB1[2], reA2[2], reB2[2];
#pragma unroll
    for (int r = 0; r < 2; r++) {
        int i = b * N + tid + (r << 10);
        rs1[r]  = d_s1[i];
        rs2[r]  = d_s2[i];
        reA1[r] = d_eA1[i];
        reB1[r] = d_eB1[i];
        reA2[r] = d_eA2[i];
        reB2[r] = d_eB2[i];
    }
    if (tid < FIN) d_v[b * FIN + tid] = 0.f;   // zero accumulator for k_wsum
    cnt2[tid] = 0;
    cnt1[tid] = 0;

    // min/max of s1, s2 (val2[0..127] as scratch)
    {
        float l1 = fminf(rs1[0], rs1[1]), h1 = fmaxf(rs1[0], rs1[1]);
        float l2 = fminf(rs2[0], rs2[1]), h2 = fmaxf(rs2[0], rs2[1]);
#pragma unroll
        for (int o = 16; o; o >>= 1) {
            l1 = fminf(l1, __shfl_xor_sync(0xffffffffu, l1, o));
            h1 = fmaxf(h1, __shfl_xor_sync(0xffffffffu, h1, o));
            l2 = fminf(l2, __shfl_xor_sync(0xffffffffu, l2, o));
            h2 = fmaxf(h2, __shfl_xor_sync(0xffffffffu, h2, o));
        }
        if (lane == 0) {
            val2[wid] = l1; val2[32 + wid] = h1;
            val2[64 + wid] = l2; val2[96 + wid] = h2;
        }
        __syncthreads();
        if (wid == 0) {
            float a0 = val2[lane], a1m = val2[32 + lane];
            float a2m = val2[64 + lane], a3 = val2[96 + lane];
#pragma unroll
            for (int o = 16; o; o >>= 1) {
                a0  = fminf(a0,  __shfl_xor_sync(0xffffffffu, a0, o));
                a1m = fmaxf(a1m, __shfl_xor_sync(0xffffffffu, a1m, o));
                a2m = fminf(a2m, __shfl_xor_sync(0xffffffffu, a2m, o));
                a3  = fmaxf(a3,  __shfl_xor_sync(0xffffffffu, a3, o));
            }
            if (lane == 0) { bc[0] = a2m; bc[1] = a3; bc[2] = a0; bc[3] = a1m; }
        }
        __syncthreads();
    }

    float lo2 = bc[0], hi2 = bc[1];
    float lo1 = bc[2], hi1 = bc[3];
    float scale2 = (hi2 > lo2) ? ((float)NB / (hi2 - lo2)) : 0.f;
    float scale1 = (hi1 > lo1) ? ((float)NB / (hi1 - lo1)) : 0.f;

    // ===== dual histogram =====
    int bn2[2], bn1[2], rk2[2], rk1[2];
#pragma unroll
    for (int r = 0; r < 2; r++) {
        bn2[r] = binOf(rs2[r], lo2, scale2);
        rk2[r] = atomicAdd(&cnt2[bn2[r]], 1);
        bn1[r] = binOf(rs1[r], lo1, scale1);
        rk1[r] = atomicAdd(&cnt1[bn1[r]], 1);
    }
    __syncthreads();

    // ===== fused dual exclusive count scan -> off2, off1 =====
    {
        int c2 = cnt2[tid], c1 = cnt1[tid];
        int i2 = c2, i1 = c1;
#pragma unroll
        for (int o = 1; o < 32; o <<= 1) {
            int y2 = __shfl_up_sync(0xffffffffu, i2, o);
            int y1 = __shfl_up_sync(0xffffffffu, i1, o);
            if (lane >= o) { i2 += y2; i1 += y1; }
        }
        if (lane == 31) { wsI[wid] = i2; wsJ[wid] = i1; }
        __syncthreads();
        if (wid == 0) {
            int w2 = wsI[lane], w1 = wsJ[lane];
            int j2 = w2, j1 = w1;
#pragma unroll
            for (int o = 1; o < 32; o <<= 1) {
                int y2 = __shfl_up_sync(0xffffffffu, j2, o);
                int y1 = __shfl_up_sync(0xffffffffu, j1, o);
                if (lane >= o) { j2 += y2; j1 += y1; }
            }
            wsI[lane] = j2 - w2; wsJ[lane] = j1 - w1;
        }
        __syncthreads();
        off2[tid] = i2 - c2 + wsI[wid];
        off1[tid] = i1 - c1 + wsJ[wid];
        if (tid == 0) { off2[NB] = N; off1[NB] = N; }
    }
    __syncthreads();

    // ===== dual scatter: struct2 key+payload (preloaded exps); struct1 key ==
    int p1s[2];
#pragma unroll
    for (int r = 0; r < 2; r++) {
        int p = off2[bn2[r]] + rk2[r];
        val2[p] = rs2[r];
        pA2[p] = reA2[r];
        pB2[p] = reB2[r];
        int q = off1[bn1[r]] + rk1[r];
        val1[q] = rs1[r];
        p1s[r] = q;
    }
    __syncthreads();

    // ===== struct2 payload bin sums + scan =====
    binscan(pA2, pB2, off2, binA, binB, wsA, wsB, bc, tid, lane, wid);
    __syncthreads();

    // ===== pass-1 queries -> g (only MUFU left: 1 RCP per element) =====
    {
        float tA = bc[4], tB = bc[5];
#pragma unroll
        for (int r = 0; r < 2; r++) {
            float s1 = rs1[r];
            float t = -s1;
            int qb = binOf(t, lo2, scale2);
            float SA = binA[qb], SB = binB[qb];
            int pe = off2[qb + 1];
            for (int p = off2[qb]; p < pe; p++) {
                if (val2[p] <= t) { SA += pA2[p]; SB += pB2[p]; }
            }
            float Apos = tA - SA;               // sum e^{s2} over s2 > -s1
            float e1 = reA1[r], e2 = reB1[r];
            float inv = 1.0f / (e1 * Apos + e2 * SB);
            pA1[p1s[r]] = e1 * inv;             // g1
            pB1[p1s[r]] = e2 * inv;             // g2
        }
    }
    __syncthreads();

    // ===== struct1 payload bin sums + scan =====
    binscan(pA1, pB1, off1, binA, binB, wsA, wsB, bc, tid, lane, wid);
    __syncthreads();

    // ===== pass-2 queries -> column mass c_j (exps preloaded) =====
    {
        float tG1 = bc[4], tG2 = bc[5];
#pragma unroll
        for (int r = 0; r < 2; r++) {
            int j = tid + (r << 10);
            float s2 = rs2[r];
            float t = -s2;
            int qb = binOf(t, lo1, scale1);
            float SG1 = binA[qb], SG2 = binB[qb];
            int pe = off1[qb + 1];
            for (int p = off1[qb]; p < pe; p++) {
                if (val1[p] <= t) { SG1 += pA1[p]; SG2 += pB1[p]; }
            }
            float P = tG1 - SG1;                // sum g1 over s1 > -s2
            float c = reA2[r] * P + reB2[r] * SG2;
            d_c[b * N + j] = c;
        }
    }
}

// ---------------- K3: v[b,:] = sum_j c[b,j] * h[b,j,:] (unchanged R14) -------
__global__ void k_wsum(const float* __restrict__ h) {
    __shared__ float red[8 * FIN];
    int b = blockIdx.x >> 6;              // grid = B*64
    int chunk = blockIdx.x & 63;
    int wid = threadIdx.x >> 5, lane = threadIdx.x & 31;   // 256 threads
    const float4* h4 = (const float4*)h;
    const float* cb = d_c + b * N;
    size_t base = (size_t)b * N * (FIN / 4);
    int j0 = chunk * 32 + wid * 4;
    float c0 = cb[j0], c1 = cb[j0 + 1], c2 = cb[j0 + 2], c3 = cb[j0 + 3];
    float4 h0 = h4[base + (size_t)(j0 + 0) * (FIN / 4) + lane];
    float4 h1 = h4[base + (size_t)(j0 + 1) * (FIN / 4) + lane];
    float4 h2 = h4[base + (size_t)(j0 + 2) * (FIN / 4) + lane];
    float4 h3 = h4[base + (size_t)(j0 + 3) * (FIN / 4) + lane];
    float4 acc;
    acc.x = c0 * h0.x + c1 * h1.x + c2 * h2.x + c3 * h3.x;
    acc.y = c0 * h0.y + c1 * h1.y + c2 * h2.y + c3 * h3.y;
    acc.z = c0 * h0.z + c1 * h1.z + c2 * h2.z + c3 * h3.z;
    acc.w = c0 * h0.w + c1 * h1.w + c2 * h2.w + c3 * h3.w;
    ((float4*)red)[wid * 32 + lane] = acc;
    __syncthreads();
    if (threadIdx.x < FIN) {
        int k = threadIdx.x;
        float s = 0.f;
#pragma unroll
        for (int w = 0; w < 8; w++) s += red[w * FIN + k];
        atomicAdd(&d_v[b * FIN + k], s);
    }
}

// ---------------- K4: out[b,f] = (1/N) * v[b,:] . W[:,f] (unchanged R14) ----
__global__ void k_out(const float* __restrict__ W, float* __restrict__ out) {
    __shared__ float sv[FIN];
    __shared__ float part[8][FOUT];
    int b = blockIdx.x;
    int tid = threadIdx.x;                // 512
    int f = tid & 63, kg = tid >> 6;      // kg in 0..7
    if (tid < FIN) sv[tid] = d_v[b * FIN + tid];
    __syncthreads();
    float acc = 0.f;
#pragma unroll
    for (int q = 0; q < 16; q++) {
        int k = kg * 16 + q;
        acc = fmaf(sv[k], W[k * FOUT + f], acc);
    }
    part[kg][f] = acc;
    __syncthreads();
    if (tid < FOUT) {
        float s = 0.f;
#pragma unroll
        for (int g = 0; g < 8; g++) s += part[g][tid];
        out[b * FOUT + tid] = s * (1.0f / (float)N);
    }
}

extern "C" void kernel_launch(void* const* d_in, const int* in_sizes, int n_in,
                              void* d_out, int out_size) {
    (void)in_sizes; (void)n_in; (void)out_size;
    const float* h = (const float*)d_in[0];
    const float* W = (const float*)d_in[1];
    const float* a = (const float*)d_in[2];
    float* out = (float*)d_out;

    cudaFuncSetAttribute(k_attn, cudaFuncAttributeMaxDynamicSharedMemorySize, SMEM_ATTN);

    k_scores<<<128, 256>>>(h, W, a);
    k_attn<<<B, 1024, SMEM_ATTN>>>();
    k_wsum<<<B * 64, 256>>>(h);
    k_out<<<B, 512>>>(W, out);
}